// round 13
// baseline (speedup 1.0000x reference)
#include <cuda_runtime.h>
#include <cuda_fp16.h>
#include <math.h>
#include <stdint.h>

// ---------------- problem constants ----------------
#define NB   128
#define TT   100
#define SS   128
#define AAd  32
#define LL   1024
#define GG   3072
#define TENC 98
#define TDEC 49
#define MDEC (TDEC*NB)

// recurrence kernel geometry (fp16 single-plane, 128-col chunks)
#define RCTAS  128
#define HPC    8
#define NT     3
#define KS     64
#define CHUNKS 8
#define APITCH 68                    // u32 per staged row (272B)
#define APLANE (128*APITCH)
#define ABUF   APLANE
#define SW_U32 (KS*NT*32*2)
#define SA_OFF (SW_U32 + 64)
#define SMEM2  ((SA_OFF + 3*ABUF)*4) // ~154 KB

// ---------------- device scratch ----------------
__device__ float    g_xbuf  [TENC*NB*160];
__device__ float    g_xg_enc[TENC*(size_t)NB*GG];
__device__ float    g_abuf  [TDEC*NB*AAd];
__device__ float    g_xg_dec[TDEC*(size_t)NB*GG];
__device__ unsigned g_hfp   [2][NB*512];   // h as fp16x2, ping-pong
__device__ float    g_hf    [NB*LL];
__device__ float    g_muparts[4*NB*LL];
__device__ float    g_lvparts[4*NB*LL];
__device__ float    g_emb   [NB*LL];
__device__ float    g_decout[TDEC*(size_t)NB*LL];
__device__ float    g_y1    [MDEC*128];
__device__ float    g_y2    [MDEC*64];
__device__ float    g_shat  [MDEC*128];
__device__ float    g_part  [MDEC];
__device__ int      g_end   [NB];
__device__ int      g_start [NB];
__device__ int      g_perm_enc[NB];
__device__ int      g_esort_enc[NB];
__device__ int      g_perm_dec[NB];
__device__ int      g_esort_dec[NB];
__device__ unsigned g_gc[8*32];            // 8 group counters, 128B apart

// ---------------- fp16 helpers ----------------
__device__ __forceinline__ unsigned packh(float x, float y) {
    unsigned r;
    asm("cvt.rn.f16x2.f32 %0, %1, %2;" : "=r"(r) : "f"(y), "f"(x));  // lo=x, hi=y
    return r;
}
__device__ __forceinline__ float2 unpackh(unsigned p) {
    __half2 h = *reinterpret_cast<__half2*>(&p);
    return __half22float2(h);
}

__device__ __forceinline__ void mma16816h(float* c, const uint32_t* a,
                                          uint32_t b0, uint32_t b1) {
    asm volatile(
        "mma.sync.aligned.m16n8k16.row.col.f32.f16.f16.f32 "
        "{%0,%1,%2,%3}, {%4,%5,%6,%7}, {%8,%9}, {%0,%1,%2,%3};"
        : "+f"(c[0]), "+f"(c[1]), "+f"(c[2]), "+f"(c[3])
        : "r"(a[0]), "r"(a[1]), "r"(a[2]), "r"(a[3]), "r"(b0), "r"(b1));
}
#define LDMX4(a, addr) asm volatile(                                        \
    "ldmatrix.sync.aligned.m8n8.x4.shared.b16 {%0,%1,%2,%3}, [%4];"         \
    : "=r"((a)[0]), "=r"((a)[1]), "=r"((a)[2]), "=r"((a)[3]) : "r"(addr))

__device__ __forceinline__ uint32_t smem_u32(const void* p) {
    uint32_t a;
    asm("{ .reg .u64 t; cvta.to.shared.u64 t, %1; cvt.u32.u64 %0, t; }"
        : "=r"(a) : "l"(p));
    return a;
}
__device__ __forceinline__ void cp16(uint32_t s, const void* g) {
    asm volatile("cp.async.cg.shared.global [%0], [%1], 16;" :: "r"(s), "l"(g));
}
__device__ __forceinline__ void cp_commit() { asm volatile("cp.async.commit_group;"); }
template<int N> __device__ __forceinline__ void cp_wait() {
    asm volatile("cp.async.wait_group %0;" :: "n"(N));
}
__device__ __forceinline__ unsigned ld_acq(const unsigned* p) {
    unsigned v;
    asm volatile("ld.acquire.gpu.global.u32 %0, [%1];" : "=r"(v) : "l"(p));
    return v;
}
__device__ __forceinline__ void red_rel(unsigned* p) {
    asm volatile("red.release.gpu.global.add.u32 [%0], 1;" :: "l"(p) : "memory");
}

__device__ __forceinline__ float sigmf_(float x) { return 1.f / (1.f + __expf(-x)); }
__device__ __forceinline__ float tanhf_(float x) {
    float e = __expf(2.f * fabsf(x));
    return copysignf(1.f - 2.f / (e + 1.f), x);
}

// stage one 128-k-col chunk (single fp16 plane), only the first rows16 rows
__device__ __forceinline__ void stage_chunk(uint32_t sbuf, const unsigned* hP,
                                            int c, int tid, int rows16)
{
    #pragma unroll
    for (int r = 0; r < 8; r++) {
        int j = tid + r*256;
        int row = j >> 4, seg = j & 15;
        if (row < rows16) {
            cp16(sbuf + row*272 + seg*16,
                 (const char*)hP + row*2048 + c*256 + seg*16);
        }
    }
    cp_commit();
}

// ============ persistent GRU recurrence (group-pipelined flags) ============
__global__ __launch_bounds__(256, 1)
void gru_persist(const float* __restrict__ Whh,
                 const float* __restrict__ xg_all,
                 const float* __restrict__ bih,
                 const float* __restrict__ bhh,
                 int T, int mode, float* __restrict__ decout,
                 const int* __restrict__ esorted, const int* __restrict__ perm)
{
    extern __shared__ unsigned dyn[];
    unsigned* sW = dyn;
    float* sb = (float*)(dyn + SW_U32);
    uint32_t sA0 = smem_u32(dyn + SA_OFF);
    __shared__ int sE[NB];
    __shared__ int sP[NB];

    int tid = threadIdx.x;
    int hc0 = blockIdx.x * HPC;
    int rot = (blockIdx.x * 5) & 7;
    int grp = blockIdx.x >> 4;

    if (tid < NB) { sE[tid] = esorted[tid]; sP[tid] = perm[tid]; }

    // one-time weight pack (fp16 single plane)
    for (int idx = tid; idx < KS*NT*32; idx += 256) {
        int lane = idx & 31;
        int nt   = (idx >> 5) % NT;
        int ks   = idx / (NT*32);
        int t4   = lane & 3;
        int grow = nt*1024 + hc0 + (lane >> 2);
        const float* wr = Whh + (size_t)grow*LL + ks*16 + 2*t4;
        unsigned* d = sW + (size_t)idx*2;
        d[0] = packh(wr[0], wr[1]);
        d[1] = packh(wr[8], wr[9]);
    }
    if (tid < 6*HPC) {
        int gate = tid / HPC, j = tid % HPC;
        const float* src = (gate < 3) ? bih : bhh;
        sb[tid] = src[(gate % 3)*1024 + hc0 + j];
    }
    __syncthreads();

    int w = tid >> 5, lane = tid & 31;
    int g = lane >> 2, t4 = lane & 3;
    int r0 = w*16 + g, r1 = r0 + 8;
    int e0 = sE[r0], e1 = sE[r1];
    int o0 = sP[r0], o1 = sP[r1];

    int jb = 2*t4;
    int colg = hc0 + jb;
    int pidx = colg >> 1;

    int m2 = lane >> 3, r8 = lane & 7;
    uint32_t ldm_off = (uint32_t)((w*16 + ((m2 & 1) << 3) + r8)*272 + (m2 >> 1)*16);

    float hprev[4];
    {
        float2 p0 = unpackh(g_hfp[0][r0*512 + pidx]);
        float2 p1 = unpackh(g_hfp[0][r1*512 + pidx]);
        hprev[0] = p0.x; hprev[1] = p0.y;
        hprev[2] = p1.x; hprev[3] = p1.y;
    }

    // per-thread cache of last-seen group counters (skip redundant polls)
    unsigned gcache[8];
    #pragma unroll
    for (int i = 0; i < 8; i++) gcache[i] = 0u;

    #define WAITG(pp, tg) do {                                            \
        int _p = (pp); unsigned _t = (tg);                                \
        if (gcache[_p] < _t) {                                            \
            unsigned _v;                                                  \
            do { _v = ld_acq(&g_gc[_p*32]); } while (_v < _t);            \
            gcache[_p] = _v;                                              \
        } } while (0)

    #pragma unroll 1
    for (int t = 0; t < T; t++) {
        int m16 = 0;
        #pragma unroll
        for (int gg = 0; gg < 8; gg++) m16 += (sE[gg << 4] >= t) ? 1 : 0;

        if (m16 > 0) {
            int rows16 = m16 << 4;
            int rb = t & 1;
            const unsigned* hP = g_hfp[rb];
            unsigned* whP = g_hfp[rb ^ 1];
            unsigned tgt = 16u * (unsigned)t;

            int a0 = (t <= e0), a1 = (t <= e1);
            const float* xg = xg_all + (size_t)t*NB*GG;
            float2 xr0{0,0}, xz0{0,0}, xn0{0,0}, xr1{0,0}, xz1{0,0}, xn1{0,0};
            if (a0) {
                xr0 = *(const float2*)(xg + (size_t)r0*GG + colg);
                xz0 = *(const float2*)(xg + (size_t)r0*GG + 1024 + colg);
                xn0 = *(const float2*)(xg + (size_t)r0*GG + 2048 + colg);
            }
            if (a1) {
                xr1 = *(const float2*)(xg + (size_t)r1*GG + colg);
                xz1 = *(const float2*)(xg + (size_t)r1*GG + 1024 + colg);
                xn1 = *(const float2*)(xg + (size_t)r1*GG + 2048 + colg);
            }

            float acc[NT][4];
            #pragma unroll
            for (int n = 0; n < NT; n++)
                #pragma unroll
                for (int c = 0; c < 4; c++) acc[n][c] = 0.f;

            {
                int p = rot;
                WAITG(p, tgt);
                stage_chunk(sA0, hP, p, tid, rows16);
            }
            {
                int p = (1 + rot) & 7;
                WAITG(p, tgt);
                stage_chunk(sA0 + ABUF*4, hP, p, tid, rows16);
            }

            bool wact = (w < m16);
            #pragma unroll 1
            for (int c = 0; c < CHUNKS; c++) {
                if (c + 1 < CHUNKS) { cp_wait<1>(); } else { cp_wait<0>(); }
                __syncthreads();
                if (c + 2 < CHUNKS) {
                    int p = (c + 2 + rot) & 7;
                    WAITG(p, tgt);
                    stage_chunk(sA0 + (uint32_t)((c + 2) % 3)*ABUF*4, hP, p,
                                tid, rows16);
                }

                if (wact) {
                    int phys = (c + rot) & 7;
                    uint32_t hb = sA0 + (uint32_t)(c % 3)*ABUF*4 + ldm_off;
                    #pragma unroll
                    for (int ksl = 0; ksl < 8; ksl++) {
                        uint32_t a[4];
                        LDMX4(a, hb + ksl*32);
                        int ksg = phys*8 + ksl;
                        #pragma unroll
                        for (int nt = 0; nt < NT; nt++) {
                            uint2 b = *(const uint2*)(sW + (size_t)((ksg*NT + nt)*32 + lane)*2);
                            mma16816h(acc[nt], a, b.x, b.y);
                        }
                    }
                }
            }

            if (a0) {
                float rr0 = sigmf_(xr0.x + sb[jb]      + acc[0][0] + sb[24+jb]);
                float rr1 = sigmf_(xr0.y + sb[jb+1]    + acc[0][1] + sb[24+jb+1]);
                float zz0 = sigmf_(xz0.x + sb[8+jb]    + acc[1][0] + sb[32+jb]);
                float zz1 = sigmf_(xz0.y + sb[8+jb+1]  + acc[1][1] + sb[32+jb+1]);
                float nn0 = tanhf_(xn0.x + sb[16+jb]   + rr0*(acc[2][0] + sb[40+jb]));
                float nn1 = tanhf_(xn0.y + sb[16+jb+1] + rr1*(acc[2][1] + sb[40+jb+1]));
                float h0 = (1.f - zz0)*nn0 + zz0*hprev[0];
                float h1 = (1.f - zz1)*nn1 + zz1*hprev[1];
                hprev[0] = h0; hprev[1] = h1;
                whP[r0*512 + pidx] = packh(h0, h1);
                if (mode == 0) {
                    if (t == e0) { float2 v{h0, h1};
                        *(float2*)(g_hf + (size_t)o0*LL + colg) = v; }
                } else {
                    float2 v{h0, h1};   // sorted row order
                    *(float2*)(decout + ((size_t)t*NB + r0)*LL + colg) = v;
                }
            }
            if (a1) {
                float rr0 = sigmf_(xr1.x + sb[jb]      + acc[0][2] + sb[24+jb]);
                float rr1 = sigmf_(xr1.y + sb[jb+1]    + acc[0][3] + sb[24+jb+1]);
                float zz0 = sigmf_(xz1.x + sb[8+jb]    + acc[1][2] + sb[32+jb]);
                float zz1 = sigmf_(xz1.y + sb[8+jb+1]  + acc[1][3] + sb[32+jb+1]);
                float nn0 = tanhf_(xn1.x + sb[16+jb]   + rr0*(acc[2][2] + sb[40+jb]));
                float nn1 = tanhf_(xn1.y + sb[16+jb+1] + rr1*(acc[2][3] + sb[40+jb+1]));
                float h0 = (1.f - zz0)*nn0 + zz0*hprev[2];
                float h1 = (1.f - zz1)*nn1 + zz1*hprev[3];
                hprev[2] = h0; hprev[3] = h1;
                whP[r1*512 + pidx] = packh(h0, h1);
                if (mode == 0) {
                    if (t == e1) { float2 v{h0, h1};
                        *(float2*)(g_hf + (size_t)o1*LL + colg) = v; }
                } else {
                    float2 v{h0, h1};   // sorted row order
                    *(float2*)(decout + ((size_t)t*NB + r1)*LL + colg) = v;
                }
            }
            __threadfence();
        }
        __syncthreads();
        if (m16 > 0 && tid == 0) red_rel(&g_gc[grp*32]);
    }
    #undef WAITG
}

__global__ void k_zero_barrier()
{
    if (threadIdx.x < 8) g_gc[threadIdx.x * 32] = 0u;
}

// ============ fp16 single-term mma GEMM with optional dead-m-tile skip ============
__global__ __launch_bounds__(256)
void gemm_mma(const float* __restrict__ A, const float* __restrict__ B,
              float* __restrict__ C, int M, int N, int K, int lda, int ldb,
              int klen, const float* __restrict__ bias, int relu,
              const int* __restrict__ acte)
{
    __shared__ unsigned sA[128*20];
    __shared__ unsigned sB[64*20];
    int tid = threadIdx.x, lane = tid & 31, w = tid >> 5;
    int wm = w & 3, wn = w >> 2;
    int m0 = blockIdx.y*128, n0 = blockIdx.x*64;
    int k0 = blockIdx.z*klen;
    int kend = k0 + klen; if (kend > K) kend = K;
    uint32_t sAb = smem_u32(sA), sBb = smem_u32(sB);
    int m2 = lane >> 3, r8 = lane & 7;
    uint32_t frag_off = (uint32_t)((((m2 & 1) << 3) + r8)*80 + (m2 >> 1)*16);

    bool wskip = false;
    if (acte) wskip = (acte[wm*32] < (int)blockIdx.y);

    float acc[2][4][4];
    #pragma unroll
    for (int mt = 0; mt < 2; mt++)
        #pragma unroll
        for (int nt = 0; nt < 4; nt++)
            #pragma unroll
            for (int i = 0; i < 4; i++) acc[mt][nt][i] = 0.f;

    for (int kb = k0; kb < kend; kb += 32) {
        #pragma unroll
        for (int r = 0; r < 4; r++) {
            int idx = tid + r*256;
            int row = idx >> 3, c4 = idx & 7;
            float4 v = *(const float4*)(A + (size_t)(m0+row)*lda + kb + c4*4);
            unsigned* d = sA + row*20 + c4*2;
            d[0] = packh(v.x, v.y);
            d[1] = packh(v.z, v.w);
        }
        #pragma unroll
        for (int r = 0; r < 2; r++) {
            int idx = tid + r*256;
            int row = idx >> 3, c4 = idx & 7;
            float4 v = *(const float4*)(B + (size_t)(n0+row)*ldb + kb + c4*4);
            unsigned* d = sB + row*20 + c4*2;
            d[0] = packh(v.x, v.y);
            d[1] = packh(v.z, v.w);
        }
        __syncthreads();
        if (!wskip) {
            #pragma unroll
            for (int kk = 0; kk < 2; kk++) {
                uint32_t ah[2][4], bh[2][4];
                #pragma unroll
                for (int mt = 0; mt < 2; mt++) {
                    uint32_t ad = sAb + (uint32_t)((wm*32 + mt*16)*80 + kk*32) + frag_off;
                    LDMX4(ah[mt], ad);
                }
                #pragma unroll
                for (int nh = 0; nh < 2; nh++) {
                    uint32_t bd = sBb + (uint32_t)((wn*32 + nh*16)*80 + kk*32) + frag_off;
                    LDMX4(bh[nh], bd);
                }
                #pragma unroll
                for (int mt = 0; mt < 2; mt++)
                    #pragma unroll
                    for (int nt = 0; nt < 4; nt++) {
                        int nh = nt >> 1, s = nt & 1;
                        mma16816h(acc[mt][nt], ah[mt], bh[nh][s], bh[nh][s+2]);
                    }
            }
        }
        __syncthreads();
    }

    if (wskip) return;
    float* Cz = C + (size_t)blockIdx.z * M * N;
    int cr = lane >> 2, cc = (lane & 3)*2;
    #pragma unroll
    for (int mt = 0; mt < 2; mt++)
        #pragma unroll
        for (int nt = 0; nt < 4; nt++) {
            int gm = m0 + wm*32 + mt*16 + cr;
            int gn = n0 + wn*32 + nt*8 + cc;
            float b0 = 0.f, b1 = 0.f;
            if (bias) { b0 = bias[gn]; b1 = bias[gn+1]; }
            float v0 = acc[mt][nt][0] + b0, v1 = acc[mt][nt][1] + b1;
            float v2 = acc[mt][nt][2] + b0, v3 = acc[mt][nt][3] + b1;
            if (relu) {
                v0 = fmaxf(v0, 0.f); v1 = fmaxf(v1, 0.f);
                v2 = fmaxf(v2, 0.f); v3 = fmaxf(v3, 0.f);
            }
            float2 p0; p0.x = v0; p0.y = v1;
            float2 p1; p1.x = v2; p1.y = v3;
            *(float2*)(Cz + (size_t)gm*N + gn) = p0;
            *(float2*)(Cz + (size_t)(gm+8)*N + gn) = p1;
        }
}

// ---------------- small kernels ----------------
__global__ void k_prep(const float* __restrict__ s)
{
    __shared__ int sEnd[NB];
    int n = threadIdx.x;
    if (n >= NB) return;
    int end = 0;
    for (int t = 1; t < TT; t++) {
        const float* p = s + ((size_t)n*TT + t)*SS;
        bool allz = true;
        for (int k = 0; k < SS; k++) { if (p[k] != 0.f) { allz = false; break; } }
        if (allz) { end = t - 1; break; }
    }
    g_end[n] = end;
    g_start[n] = end + 2;
    sEnd[n] = end;
    __syncthreads();
    int r_enc = 0, r_dec = 0;
    for (int j = 0; j < NB; j++) {
        int ej = sEnd[j];
        r_enc += (ej > end) || (ej == end && j < n);
        r_dec += (ej < end) || (ej == end && j < n);
    }
    g_perm_enc[r_enc]  = n;  g_esort_enc[r_enc] = end;
    g_perm_dec[r_dec]  = n;  g_esort_dec[r_dec] = 97 - end;
}

__global__ void k_seed_ones()
{
    int idx = blockIdx.x*blockDim.x + threadIdx.x;
    if (idx < NB*512) g_hfp[0][idx] = 0x3C003C00u;   // fp16 (1.0, 1.0)
}

__global__ void k_seed_emb()
{
    int idx = blockIdx.x*blockDim.x + threadIdx.x;
    if (idx >= NB*512) return;
    int row = idx >> 9;
    int orig = g_perm_dec[row];
    float2 e = ((const float2*)g_emb)[(size_t)orig*512 + (idx & 511)];
    g_hfp[0][idx] = packh(e.x, e.y);
}

__global__ void k_gather_enc(const float* __restrict__ s, const float* __restrict__ a)
{
    int idx = blockIdx.x*blockDim.x + threadIdx.x;
    if (idx >= TENC*NB*160) return;
    int k = idx % 160;
    int n = (idx/160) % NB;
    int t = idx / (160*NB);
    int orig = g_perm_enc[n];
    g_xbuf[idx] = (k < SS) ? s[((size_t)orig*TT+t)*SS + k]
                           : a[((size_t)orig*TT+t)*AAd + (k-SS)];
}

__global__ void k_gather_dec(const float* __restrict__ a)
{
    int idx = blockIdx.x*blockDim.x + threadIdx.x;
    if (idx >= TDEC*NB*AAd) return;
    int k = idx % AAd;
    int n = (idx/AAd) % NB;
    int t = idx / (AAd*NB);
    int orig = g_perm_dec[n];
    int src = (t + g_start[orig]) % TT;
    g_abuf[idx] = a[((size_t)orig*TT+src)*AAd + k];
}

__global__ void k_emb(const float* __restrict__ mu_b, const float* __restrict__ lv_b,
                      const float* __restrict__ eps)
{
    int idx = blockIdx.x*blockDim.x + threadIdx.x;
    if (idx >= NB*LL) return;
    int z = idx & 1023;
    float mu = mu_b[z], lv = lv_b[z];
    #pragma unroll
    for (int ks = 0; ks < 4; ks++) {
        mu += g_muparts[(size_t)ks*NB*LL + idx];
        lv += g_lvparts[(size_t)ks*NB*LL + idx];
    }
    g_emb[idx] = mu + expf(0.5f*lv)*eps[idx];
}

// loss over SORTED (t, n) rows; permutation applied here
__global__ void k_loss(const float* __restrict__ s_next)
{
    int bid = blockIdx.x;
    int t = bid >> 7, n = bid & 127;
    int orig = g_perm_dec[n];
    int st = g_start[orig];
    int j = threadIdx.x;
    float v = 0.f;
    if (t < TT - st) {
        float pred = g_shat[(size_t)bid*SS + j];
        int src = (t + st) % TT;
        v = fabsf(s_next[((size_t)orig*TT+src)*SS + j] - pred);
    }
    __shared__ float sm[128];
    sm[j] = v; __syncthreads();
    for (int s2 = 64; s2 > 0; s2 >>= 1) {
        if (j < s2) sm[j] += sm[j+s2];
        __syncthreads();
    }
    if (j == 0) g_part[bid] = sm[0];
}

__global__ void k_reduce(float* __restrict__ out)
{
    __shared__ float sm[256];
    float acc = 0.f;
    for (int i = threadIdx.x; i < MDEC; i += 256) acc += g_part[i];
    sm[threadIdx.x] = acc; __syncthreads();
    for (int s2 = 128; s2 > 0; s2 >>= 1) {
        if (threadIdx.x < s2) sm[threadIdx.x] += sm[threadIdx.x+s2];
        __syncthreads();
    }
    if (threadIdx.x == 0) out[0] = sm[0];
}

// ---------------- host orchestration ----------------
extern "C" void kernel_launch(void* const* d_in, const int* in_sizes, int n_in,
                              void* d_out, int out_size)
{
    const float* s       = (const float*)d_in[0];
    const float* a       = (const float*)d_in[1];
    const float* s_next  = (const float*)d_in[3];
    const float* eps     = (const float*)d_in[4];
    const float* enc_Wih = (const float*)d_in[5];
    const float* enc_Whh = (const float*)d_in[6];
    const float* enc_bih = (const float*)d_in[7];
    const float* enc_bhh = (const float*)d_in[8];
    const float* mu_W    = (const float*)d_in[9];
    const float* mu_b    = (const float*)d_in[10];
    const float* lv_W    = (const float*)d_in[11];
    const float* lv_b    = (const float*)d_in[12];
    const float* dec_Wih = (const float*)d_in[19];
    const float* dec_Whh = (const float*)d_in[20];
    const float* dec_bih = (const float*)d_in[21];
    const float* dec_bhh = (const float*)d_in[22];
    const float* d1_W    = (const float*)d_in[23];
    const float* d1_b    = (const float*)d_in[24];
    const float* d2_W    = (const float*)d_in[25];
    const float* d2_b    = (const float*)d_in[26];
    const float* d3_W    = (const float*)d_in[27];
    const float* d3_b    = (const float*)d_in[28];

    float *xbuf, *xg_enc, *abuf, *xg_dec, *hf;
    float *muparts, *lvparts, *emb, *decout, *y1, *y2, *shat;
    int *pe, *ee, *pd, *ed;
    cudaGetSymbolAddress((void**)&xbuf,    g_xbuf);
    cudaGetSymbolAddress((void**)&xg_enc,  g_xg_enc);
    cudaGetSymbolAddress((void**)&abuf,    g_abuf);
    cudaGetSymbolAddress((void**)&xg_dec,  g_xg_dec);
    cudaGetSymbolAddress((void**)&hf,      g_hf);
    cudaGetSymbolAddress((void**)&muparts, g_muparts);
    cudaGetSymbolAddress((void**)&lvparts, g_lvparts);
    cudaGetSymbolAddress((void**)&emb,     g_emb);
    cudaGetSymbolAddress((void**)&decout,  g_decout);
    cudaGetSymbolAddress((void**)&y1,      g_y1);
    cudaGetSymbolAddress((void**)&y2,      g_y2);
    cudaGetSymbolAddress((void**)&shat,    g_shat);
    cudaGetSymbolAddress((void**)&pe,      g_perm_enc);
    cudaGetSymbolAddress((void**)&ee,      g_esort_enc);
    cudaGetSymbolAddress((void**)&pd,      g_perm_dec);
    cudaGetSymbolAddress((void**)&ed,      g_esort_dec);

    cudaFuncSetAttribute(gru_persist, cudaFuncAttributeMaxDynamicSharedMemorySize,
                         SMEM2);

    // split points + sort + encoder init
    k_prep<<<1, 128>>>(s);
    k_seed_ones<<<(NB*512 + 255)/256, 256>>>();

    // encoder input projection (enc-sorted rows, dead-warp skip)
    k_gather_enc<<<(TENC*NB*160 + 255)/256, 256>>>(s, a);
    gemm_mma<<<dim3(GG/64, TENC*NB/128, 1), 256>>>(xbuf, enc_Wih, xg_enc,
        TENC*NB, GG, 160, 160, 160, 160, nullptr, 0, ee);

    // encoder recurrence (group-pipelined flags)
    k_zero_barrier<<<1, 32>>>();
    gru_persist<<<RCTAS, 256, SMEM2>>>(enc_Whh, xg_enc, enc_bih, enc_bhh,
                                       TENC, 0, nullptr, ee, pe);

    // reparametrize
    gemm_mma<<<dim3(LL/64, 1, 4), 256>>>(hf, mu_W, muparts,
        NB, LL, LL, LL, LL, LL/4, nullptr, 0, nullptr);
    gemm_mma<<<dim3(LL/64, 1, 4), 256>>>(hf, lv_W, lvparts,
        NB, LL, LL, LL, LL, LL/4, nullptr, 0, nullptr);
    k_emb<<<(NB*LL + 255)/256, 256>>>(mu_b, lv_b, eps);
    k_seed_emb<<<(NB*512 + 255)/256, 256>>>();

    // decoder input projection (dec-sorted rows, dead-warp skip)
    k_gather_dec<<<(TDEC*NB*AAd + 255)/256, 256>>>(a);
    gemm_mma<<<dim3(GG/64, MDEC/128, 1), 256>>>(abuf, dec_Wih, xg_dec,
        MDEC, GG, AAd, AAd, AAd, AAd, nullptr, 0, ed);

    // decoder recurrence (decout kept in SORTED row order)
    k_zero_barrier<<<1, 32>>>();
    gru_persist<<<RCTAS, 256, SMEM2>>>(dec_Whh, xg_dec, dec_bih, dec_bhh,
                                       TDEC, 1, decout, ed, pd);

    // decoder MLP head (sorted rows, dead-warp skip, fused bias+relu)
    gemm_mma<<<dim3(128/64, MDEC/128, 1), 256>>>(decout, d1_W, y1,
        MDEC, 128, LL, LL, LL, LL, d1_b, 1, ed);
    gemm_mma<<<dim3(1, MDEC/128, 1), 256>>>(y1, d2_W, y2,
        MDEC, 64, 128, 128, 128, 128, d2_b, 1, ed);
    gemm_mma<<<dim3(128/64, MDEC/128, 1), 256>>>(y2, d3_W, shat,
        MDEC, 128, 64, 64, 64, 64, d3_b, 0, ed);

    // masked L1 loss (sorted rows; permutation applied in k_loss)
    k_loss<<<MDEC, 128>>>(s_next);
    k_reduce<<<1, 256>>>((float*)d_out);
}

// round 14
// speedup vs baseline: 1.3111x; 1.3111x over previous
#include <cuda_runtime.h>
#include <cuda_fp16.h>
#include <math.h>
#include <stdint.h>

// ---------------- problem constants ----------------
#define NB   128
#define TT   100
#define SS   128
#define AAd  32
#define LL   1024
#define GG   3072
#define TENC 98
#define TDEC 49
#define MDEC (TDEC*NB)

// recurrence kernel geometry (fp16 single-plane, 128-col chunks, 4 buffers)
#define RCTAS  128
#define HPC    8
#define NT     3
#define KS     64
#define CHUNKS 8
#define APITCH 68                    // u32 per staged row (272B)
#define APLANE (128*APITCH)
#define ABUF   APLANE
#define SW_U32 (KS*NT*32*2)
#define SA_OFF (SW_U32 + 64)
#define SMEM2  ((SA_OFF + 4*ABUF)*4) // ~184 KB

// ---------------- device scratch ----------------
__device__ float    g_xbuf  [TENC*NB*160];
__device__ float    g_xg_enc[TENC*(size_t)NB*GG];
__device__ float    g_abuf  [TDEC*NB*AAd];
__device__ float    g_xg_dec[TDEC*(size_t)NB*GG];
__device__ unsigned g_hfp   [2][NB*512];   // h as fp16x2, ping-pong
__device__ float    g_hf    [NB*LL];
__device__ float    g_muparts[4*NB*LL];
__device__ float    g_lvparts[4*NB*LL];
__device__ float    g_emb   [NB*LL];
__device__ float    g_decout[TDEC*(size_t)NB*LL];
__device__ float    g_y1    [MDEC*128];
__device__ float    g_y2    [MDEC*64];
__device__ float    g_shat  [MDEC*128];
__device__ float    g_part  [MDEC];
__device__ int      g_end   [NB];
__device__ int      g_start [NB];
__device__ int      g_perm_enc[NB];
__device__ int      g_esort_enc[NB];
__device__ int      g_perm_dec[NB];
__device__ int      g_esort_dec[NB];
__device__ unsigned g_barrier;

// ---------------- fp16 helpers ----------------
__device__ __forceinline__ unsigned packh(float x, float y) {
    unsigned r;
    asm("cvt.rn.f16x2.f32 %0, %1, %2;" : "=r"(r) : "f"(y), "f"(x));  // lo=x, hi=y
    return r;
}
__device__ __forceinline__ float2 unpackh(unsigned p) {
    __half2 h = *reinterpret_cast<__half2*>(&p);
    return __half22float2(h);
}

__device__ __forceinline__ void mma16816h(float* c, const uint32_t* a,
                                          uint32_t b0, uint32_t b1) {
    asm volatile(
        "mma.sync.aligned.m16n8k16.row.col.f32.f16.f16.f32 "
        "{%0,%1,%2,%3}, {%4,%5,%6,%7}, {%8,%9}, {%0,%1,%2,%3};"
        : "+f"(c[0]), "+f"(c[1]), "+f"(c[2]), "+f"(c[3])
        : "r"(a[0]), "r"(a[1]), "r"(a[2]), "r"(a[3]), "r"(b0), "r"(b1));
}
#define LDMX4(a, addr) asm volatile(                                        \
    "ldmatrix.sync.aligned.m8n8.x4.shared.b16 {%0,%1,%2,%3}, [%4];"         \
    : "=r"((a)[0]), "=r"((a)[1]), "=r"((a)[2]), "=r"((a)[3]) : "r"(addr))

__device__ __forceinline__ uint32_t smem_u32(const void* p) {
    uint32_t a;
    asm("{ .reg .u64 t; cvta.to.shared.u64 t, %1; cvt.u32.u64 %0, t; }"
        : "=r"(a) : "l"(p));
    return a;
}
__device__ __forceinline__ void cp16(uint32_t s, const void* g) {
    asm volatile("cp.async.cg.shared.global [%0], [%1], 16;" :: "r"(s), "l"(g));
}
__device__ __forceinline__ void cp_commit() { asm volatile("cp.async.commit_group;"); }
template<int N> __device__ __forceinline__ void cp_wait() {
    asm volatile("cp.async.wait_group %0;" :: "n"(N));
}

__device__ __forceinline__ float sigmf_(float x) { return 1.f / (1.f + __expf(-x)); }
__device__ __forceinline__ float tanhf_(float x) {
    float e = __expf(2.f * fabsf(x));
    return copysignf(1.f - 2.f / (e + 1.f), x);
}

// stage one 128-k-col chunk (single fp16 plane), only the first rows16 rows
__device__ __forceinline__ void stage_chunk(uint32_t sbuf, const unsigned* hP,
                                            int c, int tid, int rows16)
{
    #pragma unroll
    for (int r = 0; r < 8; r++) {
        int j = tid + r*256;
        int row = j >> 4, seg = j & 15;
        if (row < rows16) {
            cp16(sbuf + row*272 + seg*16,
                 (const char*)hP + row*2048 + c*256 + seg*16);
        }
    }
    cp_commit();
}

// ============ persistent GRU recurrence (fp16, depth-3 pipeline) ============
__global__ __launch_bounds__(256, 1)
void gru_persist(const float* __restrict__ Whh,
                 const float* __restrict__ xg_all,
                 const float* __restrict__ bih,
                 const float* __restrict__ bhh,
                 int T, int mode, float* __restrict__ decout,
                 const int* __restrict__ esorted, const int* __restrict__ perm)
{
    extern __shared__ unsigned dyn[];
    unsigned* sW = dyn;
    float* sb = (float*)(dyn + SW_U32);
    uint32_t sA0 = smem_u32(dyn + SA_OFF);
    __shared__ int sE[NB];
    __shared__ int sP[NB];

    int tid = threadIdx.x;
    int hc0 = blockIdx.x * HPC;
    int rot = (blockIdx.x * 5) & 7;

    if (tid < NB) { sE[tid] = esorted[tid]; sP[tid] = perm[tid]; }

    // one-time weight pack (fp16 single plane)
    for (int idx = tid; idx < KS*NT*32; idx += 256) {
        int lane = idx & 31;
        int nt   = (idx >> 5) % NT;
        int ks   = idx / (NT*32);
        int t4   = lane & 3;
        int grow = nt*1024 + hc0 + (lane >> 2);
        const float* wr = Whh + (size_t)grow*LL + ks*16 + 2*t4;
        unsigned* d = sW + (size_t)idx*2;
        d[0] = packh(wr[0], wr[1]);
        d[1] = packh(wr[8], wr[9]);
    }
    if (tid < 6*HPC) {
        int gate = tid / HPC, j = tid % HPC;
        const float* src = (gate < 3) ? bih : bhh;
        sb[tid] = src[(gate % 3)*1024 + hc0 + j];
    }
    __syncthreads();

    int w = tid >> 5, lane = tid & 31;
    int g = lane >> 2, t4 = lane & 3;
    int r0 = w*16 + g, r1 = r0 + 8;
    int e0 = sE[r0], e1 = sE[r1];
    int o0 = sP[r0], o1 = sP[r1];

    int jb = 2*t4;
    int colg = hc0 + jb;
    int pidx = colg >> 1;

    int m2 = lane >> 3, r8 = lane & 7;
    uint32_t ldm_off = (uint32_t)((w*16 + ((m2 & 1) << 3) + r8)*272 + (m2 >> 1)*16);

    float hprev[4];
    {
        float2 p0 = unpackh(g_hfp[0][r0*512 + pidx]);
        float2 p1 = unpackh(g_hfp[0][r1*512 + pidx]);
        hprev[0] = p0.x; hprev[1] = p0.y;
        hprev[2] = p1.x; hprev[3] = p1.y;
    }

    // ---- prefetch state for step 0 ----
    int m16, a0, a1;
    float2 xr0, xz0, xn0, xr1, xz1, xn1;
    {
        m16 = 0;
        #pragma unroll
        for (int gg = 0; gg < 8; gg++) m16 += (sE[gg << 4] >= 0) ? 1 : 0;
        a0 = (0 <= e0); a1 = (0 <= e1);
        xr0 = xz0 = xn0 = xr1 = xz1 = xn1 = float2{0.f, 0.f};
        const float* xg = xg_all;
        if (a0) {
            xr0 = *(const float2*)(xg + (size_t)r0*GG + colg);
            xz0 = *(const float2*)(xg + (size_t)r0*GG + 1024 + colg);
            xn0 = *(const float2*)(xg + (size_t)r0*GG + 2048 + colg);
        }
        if (a1) {
            xr1 = *(const float2*)(xg + (size_t)r1*GG + colg);
            xz1 = *(const float2*)(xg + (size_t)r1*GG + 1024 + colg);
            xn1 = *(const float2*)(xg + (size_t)r1*GG + 2048 + colg);
        }
    }

    #pragma unroll 1
    for (int t = 0; t < T; t++) {
        int act = (m16 > 0);
        if (act) {
            int rows16 = m16 << 4;
            int rb = t & 1;
            const unsigned* hP = g_hfp[rb];
            unsigned* whP = g_hfp[rb ^ 1];

            float acc[NT][4];
            #pragma unroll
            for (int n = 0; n < NT; n++)
                #pragma unroll
                for (int c = 0; c < 4; c++) acc[n][c] = 0.f;

            stage_chunk(sA0,            hP, rot,         tid, rows16);
            stage_chunk(sA0 + ABUF*4,   hP, (1+rot) & 7, tid, rows16);
            stage_chunk(sA0 + 2*ABUF*4, hP, (2+rot) & 7, tid, rows16);

            bool wact = (w < m16);
            #pragma unroll 1
            for (int c = 0; c < CHUNKS; c++) {
                if (c <= CHUNKS - 3)      { cp_wait<2>(); }
                else if (c == CHUNKS - 2) { cp_wait<1>(); }
                else                      { cp_wait<0>(); }
                __syncthreads();
                if (c + 3 < CHUNKS)
                    stage_chunk(sA0 + (uint32_t)((c + 3) % 4)*ABUF*4, hP,
                                (c + 3 + rot) & 7, tid, rows16);

                if (wact) {
                    int phys = (c + rot) & 7;
                    uint32_t hb = sA0 + (uint32_t)(c % 4)*ABUF*4 + ldm_off;
                    #pragma unroll
                    for (int ksl = 0; ksl < 8; ksl++) {
                        uint32_t a[4];
                        LDMX4(a, hb + ksl*32);
                        int ksg = phys*8 + ksl;
                        #pragma unroll
                        for (int nt = 0; nt < NT; nt++) {
                            uint2 b = *(const uint2*)(sW + (size_t)((ksg*NT + nt)*32 + lane)*2);
                            mma16816h(acc[nt], a, b.x, b.y);
                        }
                    }
                }
            }

            // gate math + h-plane write (the only cross-CTA visible state)
            if (a0) {
                float rr0 = sigmf_(xr0.x + sb[jb]      + acc[0][0] + sb[24+jb]);
                float rr1 = sigmf_(xr0.y + sb[jb+1]    + acc[0][1] + sb[24+jb+1]);
                float zz0 = sigmf_(xz0.x + sb[8+jb]    + acc[1][0] + sb[32+jb]);
                float zz1 = sigmf_(xz0.y + sb[8+jb+1]  + acc[1][1] + sb[32+jb+1]);
                float nn0 = tanhf_(xn0.x + sb[16+jb]   + rr0*(acc[2][0] + sb[40+jb]));
                float nn1 = tanhf_(xn0.y + sb[16+jb+1] + rr1*(acc[2][1] + sb[40+jb+1]));
                float h0 = (1.f - zz0)*nn0 + zz0*hprev[0];
                float h1 = (1.f - zz1)*nn1 + zz1*hprev[1];
                hprev[0] = h0; hprev[1] = h1;
                whP[r0*512 + pidx] = packh(h0, h1);
            }
            if (a1) {
                float rr0 = sigmf_(xr1.x + sb[jb]      + acc[0][2] + sb[24+jb]);
                float rr1 = sigmf_(xr1.y + sb[jb+1]    + acc[0][3] + sb[24+jb+1]);
                float zz0 = sigmf_(xz1.x + sb[8+jb]    + acc[1][2] + sb[32+jb]);
                float zz1 = sigmf_(xz1.y + sb[8+jb+1]  + acc[1][3] + sb[32+jb+1]);
                float nn0 = tanhf_(xn1.x + sb[16+jb]   + rr0*(acc[2][2] + sb[40+jb]));
                float nn1 = tanhf_(xn1.y + sb[16+jb+1] + rr1*(acc[2][3] + sb[40+jb+1]));
                float h0 = (1.f - zz0)*nn0 + zz0*hprev[2];
                float h1 = (1.f - zz1)*nn1 + zz1*hprev[3];
                hprev[2] = h0; hprev[3] = h1;
                whP[r1*512 + pidx] = packh(h0, h1);
            }
        }

        if (t + 1 < T) {
            // arrive ASAP after fencing the h-plane writes
            __threadfence();
            __syncthreads();
            if (tid == 0) atomicAdd(&g_barrier, 1u);

            // deferred per-step outputs (not read by other CTAs mid-recurrence)
            if (act) {
                if (a0) {
                    if (mode == 0) {
                        if (t == e0) { float2 v{hprev[0], hprev[1]};
                            *(float2*)(g_hf + (size_t)o0*LL + colg) = v; }
                    } else {
                        float2 v{hprev[0], hprev[1]};
                        *(float2*)(decout + ((size_t)t*NB + r0)*LL + colg) = v;
                    }
                }
                if (a1) {
                    if (mode == 0) {
                        if (t == e1) { float2 v{hprev[2], hprev[3]};
                            *(float2*)(g_hf + (size_t)o1*LL + colg) = v; }
                    } else {
                        float2 v{hprev[2], hprev[3]};
                        *(float2*)(decout + ((size_t)t*NB + r1)*LL + colg) = v;
                    }
                }
            }

            // overlapped prefetch: xg + activity for step t+1
            int tn = t + 1;
            m16 = 0;
            #pragma unroll
            for (int gg = 0; gg < 8; gg++) m16 += (sE[gg << 4] >= tn) ? 1 : 0;
            a0 = (tn <= e0); a1 = (tn <= e1);
            xr0 = xz0 = xn0 = xr1 = xz1 = xn1 = float2{0.f, 0.f};
            const float* xg = xg_all + (size_t)tn*NB*GG;
            if (a0) {
                xr0 = *(const float2*)(xg + (size_t)r0*GG + colg);
                xz0 = *(const float2*)(xg + (size_t)r0*GG + 1024 + colg);
                xn0 = *(const float2*)(xg + (size_t)r0*GG + 2048 + colg);
            }
            if (a1) {
                xr1 = *(const float2*)(xg + (size_t)r1*GG + colg);
                xz1 = *(const float2*)(xg + (size_t)r1*GG + 1024 + colg);
                xn1 = *(const float2*)(xg + (size_t)r1*GG + 2048 + colg);
            }

            if (tid == 0) {
                unsigned target = (unsigned)(RCTAS*(t + 1));
                unsigned v;
                do {
                    asm volatile("ld.global.cg.u32 %0, [%1];" : "=r"(v) : "l"(&g_barrier));
                } while (v < target);
                __threadfence();
            }
            __syncthreads();
        } else if (act) {
            // last step: write outputs directly
            if (a0) {
                if (mode == 0) {
                    if (t == e0) { float2 v{hprev[0], hprev[1]};
                        *(float2*)(g_hf + (size_t)o0*LL + colg) = v; }
                } else {
                    float2 v{hprev[0], hprev[1]};
                    *(float2*)(decout + ((size_t)t*NB + r0)*LL + colg) = v;
                }
            }
            if (a1) {
                if (mode == 0) {
                    if (t == e1) { float2 v{hprev[2], hprev[3]};
                        *(float2*)(g_hf + (size_t)o1*LL + colg) = v; }
                } else {
                    float2 v{hprev[2], hprev[3]};
                    *(float2*)(decout + ((size_t)t*NB + r1)*LL + colg) = v;
                }
            }
        }
    }
}

__global__ void k_zero_barrier() { if (threadIdx.x == 0) g_barrier = 0u; }

// ============ fp16 single-term mma GEMM with optional dead-m-tile skip ============
__global__ __launch_bounds__(256)
void gemm_mma(const float* __restrict__ A, const float* __restrict__ B,
              float* __restrict__ C, int M, int N, int K, int lda, int ldb,
              int klen, const float* __restrict__ bias, int relu,
              const int* __restrict__ acte)
{
    __shared__ unsigned sA[128*20];
    __shared__ unsigned sB[64*20];
    int tid = threadIdx.x, lane = tid & 31, w = tid >> 5;
    int wm = w & 3, wn = w >> 2;
    int m0 = blockIdx.y*128, n0 = blockIdx.x*64;
    int k0 = blockIdx.z*klen;
    int kend = k0 + klen; if (kend > K) kend = K;
    uint32_t sAb = smem_u32(sA), sBb = smem_u32(sB);
    int m2 = lane >> 3, r8 = lane & 7;
    uint32_t frag_off = (uint32_t)((((m2 & 1) << 3) + r8)*80 + (m2 >> 1)*16);

    bool wskip = false;
    if (acte) wskip = (acte[wm*32] < (int)blockIdx.y);

    float acc[2][4][4];
    #pragma unroll
    for (int mt = 0; mt < 2; mt++)
        #pragma unroll
        for (int nt = 0; nt < 4; nt++)
            #pragma unroll
            for (int i = 0; i < 4; i++) acc[mt][nt][i] = 0.f;

    for (int kb = k0; kb < kend; kb += 32) {
        #pragma unroll
        for (int r = 0; r < 4; r++) {
            int idx = tid + r*256;
            int row = idx >> 3, c4 = idx & 7;
            float4 v = *(const float4*)(A + (size_t)(m0+row)*lda + kb + c4*4);
            unsigned* d = sA + row*20 + c4*2;
            d[0] = packh(v.x, v.y);
            d[1] = packh(v.z, v.w);
        }
        #pragma unroll
        for (int r = 0; r < 2; r++) {
            int idx = tid + r*256;
            int row = idx >> 3, c4 = idx & 7;
            float4 v = *(const float4*)(B + (size_t)(n0+row)*ldb + kb + c4*4);
            unsigned* d = sB + row*20 + c4*2;
            d[0] = packh(v.x, v.y);
            d[1] = packh(v.z, v.w);
        }
        __syncthreads();
        if (!wskip) {
            #pragma unroll
            for (int kk = 0; kk < 2; kk++) {
                uint32_t ah[2][4], bh[2][4];
                #pragma unroll
                for (int mt = 0; mt < 2; mt++) {
                    uint32_t ad = sAb + (uint32_t)((wm*32 + mt*16)*80 + kk*32) + frag_off;
                    LDMX4(ah[mt], ad);
                }
                #pragma unroll
                for (int nh = 0; nh < 2; nh++) {
                    uint32_t bd = sBb + (uint32_t)((wn*32 + nh*16)*80 + kk*32) + frag_off;
                    LDMX4(bh[nh], bd);
                }
                #pragma unroll
                for (int mt = 0; mt < 2; mt++)
                    #pragma unroll
                    for (int nt = 0; nt < 4; nt++) {
                        int nh = nt >> 1, s = nt & 1;
                        mma16816h(acc[mt][nt], ah[mt], bh[nh][s], bh[nh][s+2]);
                    }
            }
        }
        __syncthreads();
    }

    if (wskip) return;
    float* Cz = C + (size_t)blockIdx.z * M * N;
    int cr = lane >> 2, cc = (lane & 3)*2;
    #pragma unroll
    for (int mt = 0; mt < 2; mt++)
        #pragma unroll
        for (int nt = 0; nt < 4; nt++) {
            int gm = m0 + wm*32 + mt*16 + cr;
            int gn = n0 + wn*32 + nt*8 + cc;
            float b0 = 0.f, b1 = 0.f;
            if (bias) { b0 = bias[gn]; b1 = bias[gn+1]; }
            float v0 = acc[mt][nt][0] + b0, v1 = acc[mt][nt][1] + b1;
            float v2 = acc[mt][nt][2] + b0, v3 = acc[mt][nt][3] + b1;
            if (relu) {
                v0 = fmaxf(v0, 0.f); v1 = fmaxf(v1, 0.f);
                v2 = fmaxf(v2, 0.f); v3 = fmaxf(v3, 0.f);
            }
            float2 p0; p0.x = v0; p0.y = v1;
            float2 p1; p1.x = v2; p1.y = v3;
            *(float2*)(Cz + (size_t)gm*N + gn) = p0;
            *(float2*)(Cz + (size_t)(gm+8)*N + gn) = p1;
        }
}

// ---------------- small kernels ----------------
// parallel split-point detection: block n, thread tt checks s[n, tt+1, :]
__global__ void k_prep1(const float* __restrict__ s)
{
    __shared__ int smin[128];
    int n = blockIdx.x;
    int tt = threadIdx.x;
    int myt = tt + 1;
    int val = TT;
    if (myt < TT) {
        const float* p = s + ((size_t)n*TT + myt)*SS;
        bool allz = true;
        for (int k = 0; k < SS; k += 4) {
            float4 v = *(const float4*)(p + k);
            if (v.x != 0.f || v.y != 0.f || v.z != 0.f || v.w != 0.f) {
                allz = false; break;
            }
        }
        if (allz) val = myt;
    }
    smin[tt] = val;
    __syncthreads();
    for (int s2 = 64; s2 > 0; s2 >>= 1) {
        if (tt < s2) smin[tt] = min(smin[tt], smin[tt + s2]);
        __syncthreads();
    }
    if (tt == 0) {
        int first = smin[0];
        int end = (first == TT) ? 0 : (first - 1);
        g_end[n] = end;
        g_start[n] = end + 2;
    }
}

// deterministic rank sort (enc: end desc; dec: end asc)
__global__ void k_prep2()
{
    __shared__ int sEnd[NB];
    int n = threadIdx.x;
    sEnd[n] = g_end[n];
    __syncthreads();
    int end = sEnd[n];
    int r_enc = 0, r_dec = 0;
    for (int j = 0; j < NB; j++) {
        int ej = sEnd[j];
        r_enc += (ej > end) || (ej == end && j < n);
        r_dec += (ej < end) || (ej == end && j < n);
    }
    g_perm_enc[r_enc]  = n;  g_esort_enc[r_enc] = end;
    g_perm_dec[r_dec]  = n;  g_esort_dec[r_dec] = 97 - end;
}

__global__ void k_seed_ones()
{
    int idx = blockIdx.x*blockDim.x + threadIdx.x;
    if (idx < NB*512) g_hfp[0][idx] = 0x3C003C00u;   // fp16 (1.0, 1.0)
}

__global__ void k_seed_emb()
{
    int idx = blockIdx.x*blockDim.x + threadIdx.x;
    if (idx >= NB*512) return;
    int row = idx >> 9;
    int orig = g_perm_dec[row];
    float2 e = ((const float2*)g_emb)[(size_t)orig*512 + (idx & 511)];
    g_hfp[0][idx] = packh(e.x, e.y);
}

__global__ void k_gather_enc(const float* __restrict__ s, const float* __restrict__ a)
{
    int idx = blockIdx.x*blockDim.x + threadIdx.x;
    if (idx >= TENC*NB*160) return;
    int k = idx % 160;
    int n = (idx/160) % NB;
    int t = idx / (160*NB);
    int orig = g_perm_enc[n];
    g_xbuf[idx] = (k < SS) ? s[((size_t)orig*TT+t)*SS + k]
                           : a[((size_t)orig*TT+t)*AAd + (k-SS)];
}

__global__ void k_gather_dec(const float* __restrict__ a)
{
    int idx = blockIdx.x*blockDim.x + threadIdx.x;
    if (idx >= TDEC*NB*AAd) return;
    int k = idx % AAd;
    int n = (idx/AAd) % NB;
    int t = idx / (AAd*NB);
    int orig = g_perm_dec[n];
    int src = (t + g_start[orig]) % TT;
    g_abuf[idx] = a[((size_t)orig*TT+src)*AAd + k];
}

__global__ void k_emb(const float* __restrict__ mu_b, const float* __restrict__ lv_b,
                      const float* __restrict__ eps)
{
    int idx = blockIdx.x*blockDim.x + threadIdx.x;
    if (idx >= NB*LL) return;
    int z = idx & 1023;
    float mu = mu_b[z], lv = lv_b[z];
    #pragma unroll
    for (int ks = 0; ks < 4; ks++) {
        mu += g_muparts[(size_t)ks*NB*LL + idx];
        lv += g_lvparts[(size_t)ks*NB*LL + idx];
    }
    g_emb[idx] = mu + expf(0.5f*lv)*eps[idx];
}

// loss over SORTED (t, n) rows; permutation applied here
__global__ void k_loss(const float* __restrict__ s_next)
{
    int bid = blockIdx.x;
    int t = bid >> 7, n = bid & 127;
    int orig = g_perm_dec[n];
    int st = g_start[orig];
    int j = threadIdx.x;
    float v = 0.f;
    if (t < TT - st) {
        float pred = g_shat[(size_t)bid*SS + j];
        int src = (t + st) % TT;
        v = fabsf(s_next[((size_t)orig*TT+src)*SS + j] - pred);
    }
    __shared__ float sm[128];
    sm[j] = v; __syncthreads();
    for (int s2 = 64; s2 > 0; s2 >>= 1) {
        if (j < s2) sm[j] += sm[j+s2];
        __syncthreads();
    }
    if (j == 0) g_part[bid] = sm[0];
}

__global__ void k_reduce(float* __restrict__ out)
{
    __shared__ float sm[256];
    float acc = 0.f;
    for (int i = threadIdx.x; i < MDEC; i += 256) acc += g_part[i];
    sm[threadIdx.x] = acc; __syncthreads();
    for (int s2 = 128; s2 > 0; s2 >>= 1) {
        if (threadIdx.x < s2) sm[threadIdx.x] += sm[threadIdx.x+s2];
        __syncthreads();
    }
    if (threadIdx.x == 0) out[0] = sm[0];
}

// ---------------- host orchestration ----------------
extern "C" void kernel_launch(void* const* d_in, const int* in_sizes, int n_in,
                              void* d_out, int out_size)
{
    const float* s       = (const float*)d_in[0];
    const float* a       = (const float*)d_in[1];
    const float* s_next  = (const float*)d_in[3];
    const float* eps     = (const float*)d_in[4];
    const float* enc_Wih = (const float*)d_in[5];
    const float* enc_Whh = (const float*)d_in[6];
    const float* enc_bih = (const float*)d_in[7];
    const float* enc_bhh = (const float*)d_in[8];
    const float* mu_W    = (const float*)d_in[9];
    const float* mu_b    = (const float*)d_in[10];
    const float* lv_W    = (const float*)d_in[11];
    const float* lv_b    = (const float*)d_in[12];
    const float* dec_Wih = (const float*)d_in[19];
    const float* dec_Whh = (const float*)d_in[20];
    const float* dec_bih = (const float*)d_in[21];
    const float* dec_bhh = (const float*)d_in[22];
    const float* d1_W    = (const float*)d_in[23];
    const float* d1_b    = (const float*)d_in[24];
    const float* d2_W    = (const float*)d_in[25];
    const float* d2_b    = (const float*)d_in[26];
    const float* d3_W    = (const float*)d_in[27];
    const float* d3_b    = (const float*)d_in[28];

    float *xbuf, *xg_enc, *abuf, *xg_dec, *hf;
    float *muparts, *lvparts, *emb, *decout, *y1, *y2, *shat;
    int *pe, *ee, *pd, *ed;
    cudaGetSymbolAddress((void**)&xbuf,    g_xbuf);
    cudaGetSymbolAddress((void**)&xg_enc,  g_xg_enc);
    cudaGetSymbolAddress((void**)&abuf,    g_abuf);
    cudaGetSymbolAddress((void**)&xg_dec,  g_xg_dec);
    cudaGetSymbolAddress((void**)&hf,      g_hf);
    cudaGetSymbolAddress((void**)&muparts, g_muparts);
    cudaGetSymbolAddress((void**)&lvparts, g_lvparts);
    cudaGetSymbolAddress((void**)&emb,     g_emb);
    cudaGetSymbolAddress((void**)&decout,  g_decout);
    cudaGetSymbolAddress((void**)&y1,      g_y1);
    cudaGetSymbolAddress((void**)&y2,      g_y2);
    cudaGetSymbolAddress((void**)&shat,    g_shat);
    cudaGetSymbolAddress((void**)&pe,      g_perm_enc);
    cudaGetSymbolAddress((void**)&ee,      g_esort_enc);
    cudaGetSymbolAddress((void**)&pd,      g_perm_dec);
    cudaGetSymbolAddress((void**)&ed,      g_esort_dec);

    cudaFuncSetAttribute(gru_persist, cudaFuncAttributeMaxDynamicSharedMemorySize,
                         SMEM2);

    // split points (parallel) + sort + encoder init
    k_prep1<<<NB, 128>>>(s);
    k_prep2<<<1, 128>>>();
    k_seed_ones<<<(NB*512 + 255)/256, 256>>>();

    // encoder input projection (enc-sorted rows, dead-warp skip)
    k_gather_enc<<<(TENC*NB*160 + 255)/256, 256>>>(s, a);
    gemm_mma<<<dim3(GG/64, TENC*NB/128, 1), 256>>>(xbuf, enc_Wih, xg_enc,
        TENC*NB, GG, 160, 160, 160, 160, nullptr, 0, ee);

    // encoder recurrence
    k_zero_barrier<<<1, 32>>>();
    gru_persist<<<RCTAS, 256, SMEM2>>>(enc_Whh, xg_enc, enc_bih, enc_bhh,
                                       TENC, 0, nullptr, ee, pe);

    // reparametrize
    gemm_mma<<<dim3(LL/64, 1, 4), 256>>>(hf, mu_W, muparts,
        NB, LL, LL, LL, LL, LL/4, nullptr, 0, nullptr);
    gemm_mma<<<dim3(LL/64, 1, 4), 256>>>(hf, lv_W, lvparts,
        NB, LL, LL, LL, LL, LL/4, nullptr, 0, nullptr);
    k_emb<<<(NB*LL + 255)/256, 256>>>(mu_b, lv_b, eps);
    k_seed_emb<<<(NB*512 + 255)/256, 256>>>();

    // decoder input projection (dec-sorted rows, dead-warp skip)
    k_gather_dec<<<(TDEC*NB*AAd + 255)/256, 256>>>(a);
    gemm_mma<<<dim3(GG/64, MDEC/128, 1), 256>>>(abuf, dec_Wih, xg_dec,
        MDEC, GG, AAd, AAd, AAd, AAd, nullptr, 0, ed);

    // decoder recurrence (decout kept in SORTED row order)
    k_zero_barrier<<<1, 32>>>();
    gru_persist<<<RCTAS, 256, SMEM2>>>(dec_Whh, xg_dec, dec_bih, dec_bhh,
                                       TDEC, 1, decout, ed, pd);

    // decoder MLP head (sorted rows, dead-warp skip, fused bias+relu)
    gemm_mma<<<dim3(128/64, MDEC/128, 1), 256>>>(decout, d1_W, y1,
        MDEC, 128, LL, LL, LL, LL, d1_b, 1, ed);
    gemm_mma<<<dim3(1, MDEC/128, 1), 256>>>(y1, d2_W, y2,
        MDEC, 64, 128, 128, 128, 128, d2_b, 1, ed);
    gemm_mma<<<dim3(128/64, MDEC/128, 1), 256>>>(y2, d3_W, shat,
        MDEC, 128, 64, 64, 64, 64, d3_b, 0, ed);

    // masked L1 loss (sorted rows; permutation applied in k_loss)
    k_loss<<<MDEC, 128>>>(s_next);
    k_reduce<<<1, 256>>>((float*)d_out);
}

// round 15
// speedup vs baseline: 1.3459x; 1.0265x over previous
#include <cuda_runtime.h>
#include <cuda_fp16.h>
#include <math.h>
#include <stdint.h>

// ---------------- problem constants ----------------
#define NB   128
#define TT   100
#define SS   128
#define AAd  32
#define LL   1024
#define GG   3072
#define TENC 98
#define TDEC 49
#define MDEC (TDEC*NB)

// recurrence kernel geometry (fp16 single-plane, 128-col chunks, 4 buffers)
#define RCTAS  128
#define HPC    8
#define NT     3
#define KS     64
#define CHUNKS 8
#define APITCH 68                    // u32 per staged row (272B)
#define APLANE (128*APITCH)
#define ABUF   APLANE
#define SW_U32 (KS*NT*32*2)
#define SA_OFF (SW_U32 + 64)
#define SMEM2  ((SA_OFF + 4*ABUF)*4) // ~184 KB

// ---------------- device scratch ----------------
__device__ float    g_xbuf  [TENC*NB*160];
__device__ float    g_xg_enc[TENC*(size_t)NB*GG];
__device__ float    g_abuf  [TDEC*NB*AAd];
__device__ float    g_xg_dec[TDEC*(size_t)NB*GG];
__device__ unsigned g_hfp   [2][NB*512];   // h as fp16x2, ping-pong
__device__ float    g_hf    [NB*LL];
__device__ float    g_muparts[4*NB*LL];
__device__ float    g_lvparts[4*NB*LL];
__device__ float    g_emb   [NB*LL];
__device__ float    g_decout[TDEC*(size_t)NB*LL];
__device__ float    g_y1    [MDEC*128];
__device__ float    g_y2    [MDEC*64];
__device__ float    g_shat  [MDEC*128];
__device__ float    g_part  [MDEC];
__device__ int      g_end   [NB];
__device__ int      g_start [NB];
__device__ int      g_perm_enc[NB];
__device__ int      g_esort_enc[NB];
__device__ int      g_perm_dec[NB];
__device__ int      g_esort_dec[NB];
__device__ unsigned g_cnt;                 // arrival counter (own line)
__device__ unsigned g_pad0[31];
__device__ unsigned g_flag;                // release flag (separate line)
__device__ unsigned g_pad1[31];

// ---------------- fp16 helpers ----------------
__device__ __forceinline__ unsigned packh(float x, float y) {
    unsigned r;
    asm("cvt.rn.f16x2.f32 %0, %1, %2;" : "=r"(r) : "f"(y), "f"(x));  // lo=x, hi=y
    return r;
}
__device__ __forceinline__ float2 unpackh(unsigned p) {
    __half2 h = *reinterpret_cast<__half2*>(&p);
    return __half22float2(h);
}

__device__ __forceinline__ void mma16816h(float* c, const uint32_t* a,
                                          uint32_t b0, uint32_t b1) {
    asm volatile(
        "mma.sync.aligned.m16n8k16.row.col.f32.f16.f16.f32 "
        "{%0,%1,%2,%3}, {%4,%5,%6,%7}, {%8,%9}, {%0,%1,%2,%3};"
        : "+f"(c[0]), "+f"(c[1]), "+f"(c[2]), "+f"(c[3])
        : "r"(a[0]), "r"(a[1]), "r"(a[2]), "r"(a[3]), "r"(b0), "r"(b1));
}
#define LDMX4(a, addr) asm volatile(                                        \
    "ldmatrix.sync.aligned.m8n8.x4.shared.b16 {%0,%1,%2,%3}, [%4];"         \
    : "=r"((a)[0]), "=r"((a)[1]), "=r"((a)[2]), "=r"((a)[3]) : "r"(addr))

__device__ __forceinline__ uint32_t smem_u32(const void* p) {
    uint32_t a;
    asm("{ .reg .u64 t; cvta.to.shared.u64 t, %1; cvt.u32.u64 %0, t; }"
        : "=r"(a) : "l"(p));
    return a;
}
__device__ __forceinline__ void cp16(uint32_t s, const void* g) {
    asm volatile("cp.async.cg.shared.global [%0], [%1], 16;" :: "r"(s), "l"(g));
}
__device__ __forceinline__ void cp_commit() { asm volatile("cp.async.commit_group;"); }
template<int N> __device__ __forceinline__ void cp_wait() {
    asm volatile("cp.async.wait_group %0;" :: "n"(N));
}

__device__ __forceinline__ float sigmf_(float x) { return 1.f / (1.f + __expf(-x)); }
__device__ __forceinline__ float tanhf_(float x) {
    float e = __expf(2.f * fabsf(x));
    return copysignf(1.f - 2.f / (e + 1.f), x);
}

// stage one 128-k-col chunk (single fp16 plane), only the first rows16 rows
__device__ __forceinline__ void stage_chunk(uint32_t sbuf, const unsigned* hP,
                                            int c, int tid, int rows16)
{
    #pragma unroll
    for (int r = 0; r < 8; r++) {
        int j = tid + r*256;
        int row = j >> 4, seg = j & 15;
        if (row < rows16) {
            cp16(sbuf + row*272 + seg*16,
                 (const char*)hP + row*2048 + c*256 + seg*16);
        }
    }
    cp_commit();
}

// ============ persistent GRU recurrence (fp16, depth-3 pipeline) ============
__global__ __launch_bounds__(256, 1)
void gru_persist(const float* __restrict__ Whh,
                 const float* __restrict__ xg_all,
                 const float* __restrict__ bih,
                 const float* __restrict__ bhh,
                 int T, int mode, float* __restrict__ decout,
                 const int* __restrict__ esorted, const int* __restrict__ perm)
{
    extern __shared__ unsigned dyn[];
    unsigned* sW = dyn;
    float* sb = (float*)(dyn + SW_U32);
    uint32_t sA0 = smem_u32(dyn + SA_OFF);
    __shared__ int sE[NB];
    __shared__ int sP[NB];

    int tid = threadIdx.x;
    int hc0 = blockIdx.x * HPC;
    int rot = (blockIdx.x * 5) & 7;

    if (tid < NB) { sE[tid] = esorted[tid]; sP[tid] = perm[tid]; }

    // one-time weight pack (fp16 single plane)
    for (int idx = tid; idx < KS*NT*32; idx += 256) {
        int lane = idx & 31;
        int nt   = (idx >> 5) % NT;
        int ks   = idx / (NT*32);
        int t4   = lane & 3;
        int grow = nt*1024 + hc0 + (lane >> 2);
        const float* wr = Whh + (size_t)grow*LL + ks*16 + 2*t4;
        unsigned* d = sW + (size_t)idx*2;
        d[0] = packh(wr[0], wr[1]);
        d[1] = packh(wr[8], wr[9]);
    }
    if (tid < 6*HPC) {
        int gate = tid / HPC, j = tid % HPC;
        const float* src = (gate < 3) ? bih : bhh;
        sb[tid] = src[(gate % 3)*1024 + hc0 + j];
    }
    __syncthreads();

    int w = tid >> 5, lane = tid & 31;
    int g = lane >> 2, t4 = lane & 3;
    int r0 = w*16 + g, r1 = r0 + 8;
    int e0 = sE[r0], e1 = sE[r1];
    int o0 = sP[r0], o1 = sP[r1];

    int jb = 2*t4;
    int colg = hc0 + jb;
    int pidx = colg >> 1;

    int m2 = lane >> 3, r8 = lane & 7;
    uint32_t ldm_off = (uint32_t)((w*16 + ((m2 & 1) << 3) + r8)*272 + (m2 >> 1)*16);

    float hprev[4];
    {
        float2 p0 = unpackh(g_hfp[0][r0*512 + pidx]);
        float2 p1 = unpackh(g_hfp[0][r1*512 + pidx]);
        hprev[0] = p0.x; hprev[1] = p0.y;
        hprev[2] = p1.x; hprev[3] = p1.y;
    }

    // ---- prefetch state for step 0 ----
    int m16, a0, a1;
    float2 xr0, xz0, xn0, xr1, xz1, xn1;
    {
        m16 = 0;
        #pragma unroll
        for (int gg = 0; gg < 8; gg++) m16 += (sE[gg << 4] >= 0) ? 1 : 0;
        a0 = (0 <= e0); a1 = (0 <= e1);
        xr0 = xz0 = xn0 = xr1 = xz1 = xn1 = float2{0.f, 0.f};
        const float* xg = xg_all;
        if (a0) {
            xr0 = *(const float2*)(xg + (size_t)r0*GG + colg);
            xz0 = *(const float2*)(xg + (size_t)r0*GG + 1024 + colg);
            xn0 = *(const float2*)(xg + (size_t)r0*GG + 2048 + colg);
        }
        if (a1) {
            xr1 = *(const float2*)(xg + (size_t)r1*GG + colg);
            xz1 = *(const float2*)(xg + (size_t)r1*GG + 1024 + colg);
            xn1 = *(const float2*)(xg + (size_t)r1*GG + 2048 + colg);
        }
    }

    #pragma unroll 1
    for (int t = 0; t < T; t++) {
        int act = (m16 > 0);
        if (act) {
            int rows16 = m16 << 4;
            int rb = t & 1;
            const unsigned* hP = g_hfp[rb];
            unsigned* whP = g_hfp[rb ^ 1];

            float acc[NT][4];
            #pragma unroll
            for (int n = 0; n < NT; n++)
                #pragma unroll
                for (int c = 0; c < 4; c++) acc[n][c] = 0.f;

            stage_chunk(sA0,            hP, rot,         tid, rows16);
            stage_chunk(sA0 + ABUF*4,   hP, (1+rot) & 7, tid, rows16);
            stage_chunk(sA0 + 2*ABUF*4, hP, (2+rot) & 7, tid, rows16);

            bool wact = (w < m16);
            #pragma unroll 1
            for (int c = 0; c < CHUNKS; c++) {
                if (c <= CHUNKS - 3)      { cp_wait<2>(); }
                else if (c == CHUNKS - 2) { cp_wait<1>(); }
                else                      { cp_wait<0>(); }
                __syncthreads();
                if (c + 3 < CHUNKS)
                    stage_chunk(sA0 + (uint32_t)((c + 3) % 4)*ABUF*4, hP,
                                (c + 3 + rot) & 7, tid, rows16);

                if (wact) {
                    int phys = (c + rot) & 7;
                    uint32_t hb = sA0 + (uint32_t)(c % 4)*ABUF*4 + ldm_off;
                    #pragma unroll
                    for (int ksl = 0; ksl < 8; ksl++) {
                        uint32_t a[4];
                        LDMX4(a, hb + ksl*32);
                        int ksg = phys*8 + ksl;
                        #pragma unroll
                        for (int nt = 0; nt < NT; nt++) {
                            uint2 b = *(const uint2*)(sW + (size_t)((ksg*NT + nt)*32 + lane)*2);
                            mma16816h(acc[nt], a, b.x, b.y);
                        }
                    }
                }
            }

            // gate math + h-plane write (the only cross-CTA visible state)
            if (a0) {
                float rr0 = sigmf_(xr0.x + sb[jb]      + acc[0][0] + sb[24+jb]);
                float rr1 = sigmf_(xr0.y + sb[jb+1]    + acc[0][1] + sb[24+jb+1]);
                float zz0 = sigmf_(xz0.x + sb[8+jb]    + acc[1][0] + sb[32+jb]);
                float zz1 = sigmf_(xz0.y + sb[8+jb+1]  + acc[1][1] + sb[32+jb+1]);
                float nn0 = tanhf_(xn0.x + sb[16+jb]   + rr0*(acc[2][0] + sb[40+jb]));
                float nn1 = tanhf_(xn0.y + sb[16+jb+1] + rr1*(acc[2][1] + sb[40+jb+1]));
                float h0 = (1.f - zz0)*nn0 + zz0*hprev[0];
                float h1 = (1.f - zz1)*nn1 + zz1*hprev[1];
                hprev[0] = h0; hprev[1] = h1;
                whP[r0*512 + pidx] = packh(h0, h1);
            }
            if (a1) {
                float rr0 = sigmf_(xr1.x + sb[jb]      + acc[0][2] + sb[24+jb]);
                float rr1 = sigmf_(xr1.y + sb[jb+1]    + acc[0][3] + sb[24+jb+1]);
                float zz0 = sigmf_(xz1.x + sb[8+jb]    + acc[1][2] + sb[32+jb]);
                float zz1 = sigmf_(xz1.y + sb[8+jb+1]  + acc[1][3] + sb[32+jb+1]);
                float nn0 = tanhf_(xn1.x + sb[16+jb]   + rr0*(acc[2][2] + sb[40+jb]));
                float nn1 = tanhf_(xn1.y + sb[16+jb+1] + rr1*(acc[2][3] + sb[40+jb+1]));
                float h0 = (1.f - zz0)*nn0 + zz0*hprev[2];
                float h1 = (1.f - zz1)*nn1 + zz1*hprev[3];
                hprev[2] = h0; hprev[3] = h1;
                whP[r1*512 + pidx] = packh(h0, h1);
            }
        }

        if (t + 1 < T) {
            // arrive ASAP after fencing the h-plane writes
            __threadfence();
            __syncthreads();
            if (tid == 0) {
                unsigned old = atomicAdd(&g_cnt, 1u);
                if (old == (unsigned)(RCTAS*(t + 1)) - 1u) {
                    asm volatile("st.global.cg.u32 [%0], %1;"
                                 :: "l"(&g_flag), "r"((unsigned)(t + 1)) : "memory");
                }
            }

            // deferred per-step outputs (not read by other CTAs mid-recurrence)
            if (act) {
                if (a0) {
                    if (mode == 0) {
                        if (t == e0) { float2 v{hprev[0], hprev[1]};
                            *(float2*)(g_hf + (size_t)o0*LL + colg) = v; }
                    } else {
                        float2 v{hprev[0], hprev[1]};
                        *(float2*)(decout + ((size_t)t*NB + r0)*LL + colg) = v;
                    }
                }
                if (a1) {
                    if (mode == 0) {
                        if (t == e1) { float2 v{hprev[2], hprev[3]};
                            *(float2*)(g_hf + (size_t)o1*LL + colg) = v; }
                    } else {
                        float2 v{hprev[2], hprev[3]};
                        *(float2*)(decout + ((size_t)t*NB + r1)*LL + colg) = v;
                    }
                }
            }

            // overlapped prefetch: xg + activity for step t+1
            int tn = t + 1;
            m16 = 0;
            #pragma unroll
            for (int gg = 0; gg < 8; gg++) m16 += (sE[gg << 4] >= tn) ? 1 : 0;
            a0 = (tn <= e0); a1 = (tn <= e1);
            xr0 = xz0 = xn0 = xr1 = xz1 = xn1 = float2{0.f, 0.f};
            const float* xg = xg_all + (size_t)tn*NB*GG;
            if (a0) {
                xr0 = *(const float2*)(xg + (size_t)r0*GG + colg);
                xz0 = *(const float2*)(xg + (size_t)r0*GG + 1024 + colg);
                xn0 = *(const float2*)(xg + (size_t)r0*GG + 2048 + colg);
            }
            if (a1) {
                xr1 = *(const float2*)(xg + (size_t)r1*GG + colg);
                xz1 = *(const float2*)(xg + (size_t)r1*GG + 1024 + colg);
                xn1 = *(const float2*)(xg + (size_t)r1*GG + 2048 + colg);
            }

            if (tid == 0) {
                unsigned v;
                do {
                    asm volatile("ld.global.cg.u32 %0, [%1];" : "=r"(v) : "l"(&g_flag));
                } while (v < (unsigned)(t + 1));
                __threadfence();
            }
            __syncthreads();
        } else if (act) {
            // last step: write outputs directly
            if (a0) {
                if (mode == 0) {
                    if (t == e0) { float2 v{hprev[0], hprev[1]};
                        *(float2*)(g_hf + (size_t)o0*LL + colg) = v; }
                } else {
                    float2 v{hprev[0], hprev[1]};
                    *(float2*)(decout + ((size_t)t*NB + r0)*LL + colg) = v;
                }
            }
            if (a1) {
                if (mode == 0) {
                    if (t == e1) { float2 v{hprev[2], hprev[3]};
                        *(float2*)(g_hf + (size_t)o1*LL + colg) = v; }
                } else {
                    float2 v{hprev[2], hprev[3]};
                    *(float2*)(decout + ((size_t)t*NB + r1)*LL + colg) = v;
                }
            }
        }
    }
}

__global__ void k_zero_barrier()
{
    if (threadIdx.x == 0) { g_cnt = 0u; g_flag = 0u; }
}

// ============ fp16 mma GEMM, register-prefetch pipelined, dead-tile skip ============
__global__ __launch_bounds__(256)
void gemm_mma(const float* __restrict__ A, const float* __restrict__ B,
              float* __restrict__ C, int M, int N, int K, int lda, int ldb,
              int klen, const float* __restrict__ bias, int relu,
              const int* __restrict__ acte)
{
    __shared__ unsigned sA[128*20];
    __shared__ unsigned sB[64*20];
    int tid = threadIdx.x, lane = tid & 31, w = tid >> 5;
    int wm = w & 3, wn = w >> 2;
    int m0 = blockIdx.y*128, n0 = blockIdx.x*64;
    int k0 = blockIdx.z*klen;
    int kend = k0 + klen; if (kend > K) kend = K;
    uint32_t sAb = smem_u32(sA), sBb = smem_u32(sB);
    int m2 = lane >> 3, r8 = lane & 7;
    uint32_t frag_off = (uint32_t)((((m2 & 1) << 3) + r8)*80 + (m2 >> 1)*16);

    bool wskip = false;
    if (acte) wskip = (acte[wm*32] < (int)blockIdx.y);

    float acc[2][4][4];
    #pragma unroll
    for (int mt = 0; mt < 2; mt++)
        #pragma unroll
        for (int nt = 0; nt < 4; nt++)
            #pragma unroll
            for (int i = 0; i < 4; i++) acc[mt][nt][i] = 0.f;

    // register-prefetch pipeline
    float4 va[4], vb[2];
    #pragma unroll
    for (int r = 0; r < 4; r++) {
        int idx = tid + r*256;
        va[r] = *(const float4*)(A + (size_t)(m0+(idx>>3))*lda + k0 + (idx&7)*4);
    }
    #pragma unroll
    for (int r = 0; r < 2; r++) {
        int idx = tid + r*256;
        vb[r] = *(const float4*)(B + (size_t)(n0+(idx>>3))*ldb + k0 + (idx&7)*4);
    }

    for (int kb = k0; kb < kend; kb += 32) {
        #pragma unroll
        for (int r = 0; r < 4; r++) {
            int idx = tid + r*256;
            unsigned* d = sA + (idx>>3)*20 + (idx&7)*2;
            d[0] = packh(va[r].x, va[r].y);
            d[1] = packh(va[r].z, va[r].w);
        }
        #pragma unroll
        for (int r = 0; r < 2; r++) {
            int idx = tid + r*256;
            unsigned* d = sB + (idx>>3)*20 + (idx&7)*2;
            d[0] = packh(vb[r].x, vb[r].y);
            d[1] = packh(vb[r].z, vb[r].w);
        }
        __syncthreads();
        if (kb + 32 < kend) {   // prefetch next k-block; overlaps mma below
            #pragma unroll
            for (int r = 0; r < 4; r++) {
                int idx = tid + r*256;
                va[r] = *(const float4*)(A + (size_t)(m0+(idx>>3))*lda + kb + 32 + (idx&7)*4);
            }
            #pragma unroll
            for (int r = 0; r < 2; r++) {
                int idx = tid + r*256;
                vb[r] = *(const float4*)(B + (size_t)(n0+(idx>>3))*ldb + kb + 32 + (idx&7)*4);
            }
        }
        if (!wskip) {
            #pragma unroll
            for (int kk = 0; kk < 2; kk++) {
                uint32_t ah[2][4], bh[2][4];
                #pragma unroll
                for (int mt = 0; mt < 2; mt++) {
                    uint32_t ad = sAb + (uint32_t)((wm*32 + mt*16)*80 + kk*32) + frag_off;
                    LDMX4(ah[mt], ad);
                }
                #pragma unroll
                for (int nh = 0; nh < 2; nh++) {
                    uint32_t bd = sBb + (uint32_t)((wn*32 + nh*16)*80 + kk*32) + frag_off;
                    LDMX4(bh[nh], bd);
                }
                #pragma unroll
                for (int mt = 0; mt < 2; mt++)
                    #pragma unroll
                    for (int nt = 0; nt < 4; nt++) {
                        int nh = nt >> 1, s = nt & 1;
                        mma16816h(acc[mt][nt], ah[mt], bh[nh][s], bh[nh][s+2]);
                    }
            }
        }
        __syncthreads();
    }

    if (wskip) return;
    float* Cz = C + (size_t)blockIdx.z * M * N;
    int cr = lane >> 2, cc = (lane & 3)*2;
    #pragma unroll
    for (int mt = 0; mt < 2; mt++)
        #pragma unroll
        for (int nt = 0; nt < 4; nt++) {
            int gm = m0 + wm*32 + mt*16 + cr;
            int gn = n0 + wn*32 + nt*8 + cc;
            float b0 = 0.f, b1 = 0.f;
            if (bias) { b0 = bias[gn]; b1 = bias[gn+1]; }
            float v0 = acc[mt][nt][0] + b0, v1 = acc[mt][nt][1] + b1;
            float v2 = acc[mt][nt][2] + b0, v3 = acc[mt][nt][3] + b1;
            if (relu) {
                v0 = fmaxf(v0, 0.f); v1 = fmaxf(v1, 0.f);
                v2 = fmaxf(v2, 0.f); v3 = fmaxf(v3, 0.f);
            }
            float2 p0; p0.x = v0; p0.y = v1;
            float2 p1; p1.x = v2; p1.y = v3;
            *(float2*)(Cz + (size_t)gm*N + gn) = p0;
            *(float2*)(Cz + (size_t)(gm+8)*N + gn) = p1;
        }
}

// ---------------- small kernels ----------------
// parallel split-point detection: block n, thread tt checks s[n, tt+1, :]
__global__ void k_prep1(const float* __restrict__ s)
{
    __shared__ int smin[128];
    int n = blockIdx.x;
    int tt = threadIdx.x;
    int myt = tt + 1;
    int val = TT;
    if (myt < TT) {
        const float* p = s + ((size_t)n*TT + myt)*SS;
        bool allz = true;
        for (int k = 0; k < SS; k += 4) {
            float4 v = *(const float4*)(p + k);
            if (v.x != 0.f || v.y != 0.f || v.z != 0.f || v.w != 0.f) {
                allz = false; break;
            }
        }
        if (allz) val = myt;
    }
    smin[tt] = val;
    __syncthreads();
    for (int s2 = 64; s2 > 0; s2 >>= 1) {
        if (tt < s2) smin[tt] = min(smin[tt], smin[tt + s2]);
        __syncthreads();
    }
    if (tt == 0) {
        int first = smin[0];
        int end = (first == TT) ? 0 : (first - 1);
        g_end[n] = end;
        g_start[n] = end + 2;
    }
}

// deterministic rank sort (enc: end desc; dec: end asc)
__global__ void k_prep2()
{
    __shared__ int sEnd[NB];
    int n = threadIdx.x;
    sEnd[n] = g_end[n];
    __syncthreads();
    int end = sEnd[n];
    int r_enc = 0, r_dec = 0;
    for (int j = 0; j < NB; j++) {
        int ej = sEnd[j];
        r_enc += (ej > end) || (ej == end && j < n);
        r_dec += (ej < end) || (ej == end && j < n);
    }
    g_perm_enc[r_enc]  = n;  g_esort_enc[r_enc] = end;
    g_perm_dec[r_dec]  = n;  g_esort_dec[r_dec] = 97 - end;
}

__global__ void k_seed_ones()
{
    int idx = blockIdx.x*blockDim.x + threadIdx.x;
    if (idx < NB*512) g_hfp[0][idx] = 0x3C003C00u;   // fp16 (1.0, 1.0)
}

__global__ void k_seed_emb()
{
    int idx = blockIdx.x*blockDim.x + threadIdx.x;
    if (idx >= NB*512) return;
    int row = idx >> 9;
    int orig = g_perm_dec[row];
    float2 e = ((const float2*)g_emb)[(size_t)orig*512 + (idx & 511)];
    g_hfp[0][idx] = packh(e.x, e.y);
}

__global__ void k_gather_enc(const float* __restrict__ s, const float* __restrict__ a)
{
    int idx = blockIdx.x*blockDim.x + threadIdx.x;
    if (idx >= TENC*NB*160) return;
    int k = idx % 160;
    int n = (idx/160) % NB;
    int t = idx / (160*NB);
    int orig = g_perm_enc[n];
    g_xbuf[idx] = (k < SS) ? s[((size_t)orig*TT+t)*SS + k]
                           : a[((size_t)orig*TT+t)*AAd + (k-SS)];
}

__global__ void k_gather_dec(const float* __restrict__ a)
{
    int idx = blockIdx.x*blockDim.x + threadIdx.x;
    if (idx >= TDEC*NB*AAd) return;
    int k = idx % AAd;
    int n = (idx/AAd) % NB;
    int t = idx / (AAd*NB);
    int orig = g_perm_dec[n];
    int src = (t + g_start[orig]) % TT;
    g_abuf[idx] = a[((size_t)orig*TT+src)*AAd + k];
}

__global__ void k_emb(const float* __restrict__ mu_b, const float* __restrict__ lv_b,
                      const float* __restrict__ eps)
{
    int idx = blockIdx.x*blockDim.x + threadIdx.x;
    if (idx >= NB*LL) return;
    int z = idx & 1023;
    float mu = mu_b[z], lv = lv_b[z];
    #pragma unroll
    for (int ks = 0; ks < 4; ks++) {
        mu += g_muparts[(size_t)ks*NB*LL + idx];
        lv += g_lvparts[(size_t)ks*NB*LL + idx];
    }
    g_emb[idx] = mu + expf(0.5f*lv)*eps[idx];
}

// loss over SORTED (t, n) rows; permutation applied here
__global__ void k_loss(const float* __restrict__ s_next)
{
    int bid = blockIdx.x;
    int t = bid >> 7, n = bid & 127;
    int orig = g_perm_dec[n];
    int st = g_start[orig];
    int j = threadIdx.x;
    float v = 0.f;
    if (t < TT - st) {
        float pred = g_shat[(size_t)bid*SS + j];
        int src = (t + st) % TT;
        v = fabsf(s_next[((size_t)orig*TT+src)*SS + j] - pred);
    }
    __shared__ float sm[128];
    sm[j] = v; __syncthreads();
    for (int s2 = 64; s2 > 0; s2 >>= 1) {
        if (j < s2) sm[j] += sm[j+s2];
        __syncthreads();
    }
    if (j == 0) g_part[bid] = sm[0];
}

__global__ void k_reduce(float* __restrict__ out)
{
    __shared__ float sm[256];
    float acc = 0.f;
    for (int i = threadIdx.x; i < MDEC; i += 256) acc += g_part[i];
    sm[threadIdx.x] = acc; __syncthreads();
    for (int s2 = 128; s2 > 0; s2 >>= 1) {
        if (threadIdx.x < s2) sm[threadIdx.x] += sm[threadIdx.x+s2];
        __syncthreads();
    }
    if (threadIdx.x == 0) out[0] = sm[0];
}

// ---------------- host orchestration ----------------
extern "C" void kernel_launch(void* const* d_in, const int* in_sizes, int n_in,
                              void* d_out, int out_size)
{
    const float* s       = (const float*)d_in[0];
    const float* a       = (const float*)d_in[1];
    const float* s_next  = (const float*)d_in[3];
    const float* eps     = (const float*)d_in[4];
    const float* enc_Wih = (const float*)d_in[5];
    const float* enc_Whh = (const float*)d_in[6];
    const float* enc_bih = (const float*)d_in[7];
    const float* enc_bhh = (const float*)d_in[8];
    const float* mu_W    = (const float*)d_in[9];
    const float* mu_b    = (const float*)d_in[10];
    const float* lv_W    = (const float*)d_in[11];
    const float* lv_b    = (const float*)d_in[12];
    const float* dec_Wih = (const float*)d_in[19];
    const float* dec_Whh = (const float*)d_in[20];
    const float* dec_bih = (const float*)d_in[21];
    const float* dec_bhh = (const float*)d_in[22];
    const float* d1_W    = (const float*)d_in[23];
    const float* d1_b    = (const float*)d_in[24];
    const float* d2_W    = (const float*)d_in[25];
    const float* d2_b    = (const float*)d_in[26];
    const float* d3_W    = (const float*)d_in[27];
    const float* d3_b    = (const float*)d_in[28];

    float *xbuf, *xg_enc, *abuf, *xg_dec, *hf;
    float *muparts, *lvparts, *emb, *decout, *y1, *y2, *shat;
    int *pe, *ee, *pd, *ed;
    cudaGetSymbolAddress((void**)&xbuf,    g_xbuf);
    cudaGetSymbolAddress((void**)&xg_enc,  g_xg_enc);
    cudaGetSymbolAddress((void**)&abuf,    g_abuf);
    cudaGetSymbolAddress((void**)&xg_dec,  g_xg_dec);
    cudaGetSymbolAddress((void**)&hf,      g_hf);
    cudaGetSymbolAddress((void**)&muparts, g_muparts);
    cudaGetSymbolAddress((void**)&lvparts, g_lvparts);
    cudaGetSymbolAddress((void**)&emb,     g_emb);
    cudaGetSymbolAddress((void**)&decout,  g_decout);
    cudaGetSymbolAddress((void**)&y1,      g_y1);
    cudaGetSymbolAddress((void**)&y2,      g_y2);
    cudaGetSymbolAddress((void**)&shat,    g_shat);
    cudaGetSymbolAddress((void**)&pe,      g_perm_enc);
    cudaGetSymbolAddress((void**)&ee,      g_esort_enc);
    cudaGetSymbolAddress((void**)&pd,      g_perm_dec);
    cudaGetSymbolAddress((void**)&ed,      g_esort_dec);

    cudaFuncSetAttribute(gru_persist, cudaFuncAttributeMaxDynamicSharedMemorySize,
                         SMEM2);

    // split points (parallel) + sort + encoder init
    k_prep1<<<NB, 128>>>(s);
    k_prep2<<<1, 128>>>();
    k_seed_ones<<<(NB*512 + 255)/256, 256>>>();

    // encoder input projection (enc-sorted rows, dead-warp skip)
    k_gather_enc<<<(TENC*NB*160 + 255)/256, 256>>>(s, a);
    gemm_mma<<<dim3(GG/64, TENC*NB/128, 1), 256>>>(xbuf, enc_Wih, xg_enc,
        TENC*NB, GG, 160, 160, 160, 160, nullptr, 0, ee);

    // encoder recurrence
    k_zero_barrier<<<1, 32>>>();
    gru_persist<<<RCTAS, 256, SMEM2>>>(enc_Whh, xg_enc, enc_bih, enc_bhh,
                                       TENC, 0, nullptr, ee, pe);

    // reparametrize
    gemm_mma<<<dim3(LL/64, 1, 4), 256>>>(hf, mu_W, muparts,
        NB, LL, LL, LL, LL, LL/4, nullptr, 0, nullptr);
    gemm_mma<<<dim3(LL/64, 1, 4), 256>>>(hf, lv_W, lvparts,
        NB, LL, LL, LL, LL, LL/4, nullptr, 0, nullptr);
    k_emb<<<(NB*LL + 255)/256, 256>>>(mu_b, lv_b, eps);
    k_seed_emb<<<(NB*512 + 255)/256, 256>>>();

    // decoder input projection (dec-sorted rows, dead-warp skip)
    k_gather_dec<<<(TDEC*NB*AAd + 255)/256, 256>>>(a);
    gemm_mma<<<dim3(GG/64, MDEC/128, 1), 256>>>(abuf, dec_Wih, xg_dec,
        MDEC, GG, AAd, AAd, AAd, AAd, nullptr, 0, ed);

    // decoder recurrence (decout kept in SORTED row order)
    k_zero_barrier<<<1, 32>>>();
    gru_persist<<<RCTAS, 256, SMEM2>>>(dec_Whh, xg_dec, dec_bih, dec_bhh,
                                       TDEC, 1, decout, ed, pd);

    // decoder MLP head (sorted rows, dead-warp skip, fused bias+relu)
    gemm_mma<<<dim3(128/64, MDEC/128, 1), 256>>>(decout, d1_W, y1,
        MDEC, 128, LL, LL, LL, LL, d1_b, 1, ed);
    gemm_mma<<<dim3(1, MDEC/128, 1), 256>>>(y1, d2_W, y2,
        MDEC, 64, 128, 128, 128, 128, d2_b, 1, ed);
    gemm_mma<<<dim3(128/64, MDEC/128, 1), 256>>>(y2, d3_W, shat,
        MDEC, 128, 64, 64, 64, 64, d3_b, 0, ed);

    // masked L1 loss (sorted rows; permutation applied in k_loss)
    k_loss<<<MDEC, 128>>>(s_next);
    k_reduce<<<1, 256>>>((float*)d_out);
}